// round 7
// baseline (speedup 1.0000x reference)
#include <cuda_runtime.h>
#include <math.h>

// Problem constants (match reference)
#define Wd 96
#define Hd 96
#define Dd 64
#define Ad 90
#define Ud 96
#define Vd 64
#define NSTEPS 194          // H + W + 2 (>= max segments 95+95+1)
#define NRAYS  (Ad * Ud)    // 8640
#define WPB    4            // warps (== rays) per block

__device__ __forceinline__ void t_for(float p0, float dp, float pmin, float pmax,
                                      float& lo, float& hi) {
    const float EPS = 1e-12f;
    bool par = fabsf(dp) < EPS;
    float safe = par ? 1.0f : dp;
    float t0 = (pmin - p0) / safe;
    float t1 = (pmax - p0) / safe;
    lo = fminf(t0, t1);
    hi = fmaxf(t0, t1);
    bool inside = (p0 >= pmin) && (p0 <= pmax);
    if (par) {
        lo = inside ? -INFINITY : INFINITY;
        hi = inside ?  INFINITY : -INFINITY;
    }
}

// One warp per ray. Phase 1: all lanes compute the ray's Siddon segments in
// closed form (merge-path over two arithmetic crossing-time sequences) into
// smem. Phase 2: float2-per-lane accumulation over v (R2-proven config).
__global__ __launch_bounds__(32 * WPB) void siddon_fused_kernel(
        const float* __restrict__ vol, float* __restrict__ out) {
    __shared__ int2 s_t[WPB][NSTEPS];

    int wr   = threadIdx.x >> 5;
    int lane = threadIdx.x & 31;
    int ray  = blockIdx.x * WPB + wr;

    int a  = ray / Ud;
    int ui = ray % Ud;

    const float EPS  = 1e-12f;
    const float DIAG = 1.41421356237309515f;

    // Ray setup (uniform across warp; computed redundantly per lane)
    const float ang_step = 3.14159274101257324f / 90.0f;
    float ang = (float)a * ang_step;
    float ct = (float)cos((double)ang);
    float st = (float)sin((double)ang);

    float u  = (float)ui - 47.5f;
    float dx = ct, dy = st;
    float x0 = -u * st;
    float y0 =  u * ct;

    const float pmin = -47.5f, pmax = 47.5f;
    float tx0, tx1, ty0, ty1;
    t_for(x0, dx, pmin, pmax, tx0, tx1);
    t_for(y0, dy, pmin, pmax, ty0, ty1);

    float t_entry = fmaxf(tx0, ty0);
    float t_exit  = fminf(tx1, ty1);
    bool  alive0  = t_entry < t_exit;
    float te  = alive0 ? t_entry : 0.0f;
    float tex = alive0 ? t_exit  : 0.0f;

    float xe = x0 + te * dx;
    float ye = y0 + te * dy;

    int i0 = (int)fminf(fmaxf(rintf(xe + 47.5f), 0.0f), (float)(Wd - 1));
    int j0 = (int)fminf(fmaxf(rintf(ye + 47.5f), 0.0f), (float)(Hd - 1));

    float wscale = DIAG / fmaxf(fabsf(dx) + fabsf(dy), EPS);

    bool okx = fabsf(dx) > EPS;
    bool oky = fabsf(dy) > EPS;
    float inv_dx = okx ? (1.0f / dx) : 0.0f;
    float inv_dy = oky ? (1.0f / dy) : 0.0f;

    float xoff = (dx > 0.0f) ? (0.5f - 47.5f) : (-0.5f - 47.5f);
    float yoff = (dy > 0.0f) ? (0.5f - 47.5f) : (-0.5f - 47.5f);
    int   istep = (dx > 0.0f) ? 1 : -1;
    int   jstep = (dy > 0.0f) ? 1 : -1;

    // Arithmetic sequences of crossing times: TX(k)=TX0+k*dtx, TY(l)=TY0+l*dty
    float TX0 = okx ? (te + (((float)i0 + xoff) - xe) * inv_dx) : INFINITY;
    float TY0 = oky ? (te + (((float)j0 + yoff) - ye) * inv_dy) : INFINITY;
    float dtx = okx ? fabsf(inv_dx) : 0.0f;
    float dty = oky ? fabsf(inv_dy) : 0.0f;

    // Counts of crossings strictly before tex
    int kx_cnt = 0;
    if (okx && TX0 < tex) {
        int k = (int)floorf((tex - TX0) / dtx) + 1;
        k = min(max(k, 0), Wd);
        while (k > 0 && fmaf((float)(k - 1), dtx, TX0) >= tex) k--;
        while (k < Wd && fmaf((float)k, dtx, TX0) < tex) k++;
        kx_cnt = k;
    }
    int ky_cnt = 0;
    if (oky && TY0 < tex) {
        int k = (int)floorf((tex - TY0) / dty) + 1;
        k = min(max(k, 0), Hd);
        while (k > 0 && fmaf((float)(k - 1), dty, TY0) >= tex) k--;
        while (k < Hd && fmaf((float)k, dty, TY0) < tex) k++;
        ky_cnt = k;
    }

    int nseg = alive0 ? min(kx_cnt + ky_cnt + 1, NSTEPS) : 0;

    // Phase 1: lanes compute segments in parallel (merge-path partition)
    for (int m = lane; m < nseg; m += 32) {
        int clo = max(0, m - ky_cnt);
        int chi = min(m, kx_cnt);
        while (clo < chi) {
            int mid = (clo + chi + 1) >> 1;
            float txv = fmaf((float)(mid - 1), dtx, TX0);
            float tyv = fmaf((float)(m - mid), dty, TY0);
            if (txv < tyv) clo = mid; else chi = mid - 1;
        }
        int cx = clo;
        int cy = m - cx;

        float S = te;
        if (m > 0) {
            float sx = (cx > 0) ? fmaf((float)(cx - 1), dtx, TX0) : -INFINITY;
            float sy = (cy > 0) ? fmaf((float)(cy - 1), dty, TY0) : -INFINITY;
            S = fmaxf(sx, sy);
        }
        float ex = (cx < kx_cnt) ? fmaf((float)cx, dtx, TX0) : INFINITY;
        float ey = (cy < ky_cnt) ? fmaf((float)cy, dty, TY0) : INFINITY;
        float E  = fminf(fminf(ex, ey), tex);

        float w = (S < tex - EPS) ? fmaxf(0.0f, (E - S) * wscale) : 0.0f;

        int i = min(max(i0 + istep * cx, 0), Wd - 1);
        int j = min(max(j0 + jstep * cy, 0), Hd - 1);

        int2 e;
        e.x = i * (Hd * Dd) + j * Dd;
        e.y = __float_as_int(w);
        s_t[wr][m] = e;
    }
    __syncwarp();

    // Phase 2: accumulate. Lane covers v = 2*lane, 2*lane+1 (float2), MLP=4.
    const float2* vp = (const float2*)vol;
    float a0x = 0.f, a0y = 0.f, a1x = 0.f, a1y = 0.f;
    float a2x = 0.f, a2y = 0.f, a3x = 0.f, a3y = 0.f;

    int n = 0;
    for (; n + 3 < nseg; n += 4) {
        int2 e0 = s_t[wr][n + 0];
        int2 e1 = s_t[wr][n + 1];
        int2 e2 = s_t[wr][n + 2];
        int2 e3 = s_t[wr][n + 3];
        float2 v0 = vp[(e0.x >> 1) + lane];
        float2 v1 = vp[(e1.x >> 1) + lane];
        float2 v2 = vp[(e2.x >> 1) + lane];
        float2 v3 = vp[(e3.x >> 1) + lane];
        float w0 = __int_as_float(e0.y);
        float w1 = __int_as_float(e1.y);
        float w2 = __int_as_float(e2.y);
        float w3 = __int_as_float(e3.y);
        a0x += v0.x * w0;  a0y += v0.y * w0;
        a1x += v1.x * w1;  a1y += v1.y * w1;
        a2x += v2.x * w2;  a2y += v2.y * w2;
        a3x += v3.x * w3;  a3y += v3.y * w3;
    }
    for (; n < nseg; n++) {
        int2 e = s_t[wr][n];
        float2 v = vp[(e.x >> 1) + lane];
        float w = __int_as_float(e.y);
        a0x += v.x * w;  a0y += v.y * w;
    }

    float2 res;
    res.x = (a0x + a1x) + (a2x + a3x);
    res.y = (a0y + a1y) + (a2y + a3y);
    // output layout (B,C,U,A,V): float2 index = (u*A + a)*32 + lane
    ((float2*)out)[(ui * Ad + a) * 32 + lane] = res;
}

extern "C" void kernel_launch(void* const* d_in, const int* in_sizes, int n_in,
                              void* d_out, int out_size) {
    const float* vol = (const float*)d_in[0];
    float* out = (float*)d_out;

    dim3 blk(32 * WPB);            // 128 threads
    dim3 grd(NRAYS / WPB);         // 2160 blocks
    siddon_fused_kernel<<<grd, blk>>>(vol, out);
}

// round 8
// speedup vs baseline: 1.9226x; 1.9226x over previous
#include <cuda_runtime.h>
#include <math.h>

// Problem constants (match reference)
#define Wd 96
#define Hd 96
#define Dd 64
#define Ad 90
#define Ud 96
#define Vd 64
#define NSTEPS 194          // H + W + 2
#define NPAD   200          // NSTEPS rounded up to multiple of 8
#define NRAYS  (Ad * Ud)    // 8640
#define WPB    4            // warps (== rays) per block in accum kernel

// Static device scratch (no allocations allowed).
// Packed trace: .x = voxel base offset (i*H*D + j*D), .y = weight bits.
__device__ int2 g_trace[NRAYS * NSTEPS];
__device__ int  g_cnt[NRAYS];

__device__ __forceinline__ void t_for(float p0, float dp, float pmin, float pmax,
                                      float& lo, float& hi) {
    const float EPS = 1e-12f;
    bool par = fabsf(dp) < EPS;
    float safe = par ? 1.0f : dp;
    float t0 = (pmin - p0) / safe;
    float t1 = (pmax - p0) / safe;
    lo = fminf(t0, t1);
    hi = fmaxf(t0, t1);
    bool inside = (p0 >= pmin) && (p0 <= pmax);
    if (par) {
        lo = inside ? -INFINITY : INFINITY;
        hi = inside ?  INFINITY : -INFINITY;
    }
}

// One thread per ray (R2-proven version: 13.6us, rel_err 9.9e-5).
__global__ __launch_bounds__(64) void siddon_trace_kernel() {
    int r = blockIdx.x * blockDim.x + threadIdx.x;
    if (r >= NRAYS) return;

    const float EPS  = 1e-12f;
    const float DIAG = 1.41421356237309515f;  // f32(sqrt(2))

    int a  = r / Ud;
    int ui = r % Ud;

    const float ang_step = 3.14159274101257324f / 90.0f;
    float ang = (float)a * ang_step;
    float ct = (float)cos((double)ang);
    float st = (float)sin((double)ang);

    float u  = (float)ui - 47.5f;
    float dx = ct, dy = st;
    float x0 = -u * st;
    float y0 =  u * ct;

    const float pmin = -47.5f, pmax = 47.5f;

    float tx0, tx1, ty0, ty1;
    t_for(x0, dx, pmin, pmax, tx0, tx1);
    t_for(y0, dy, pmin, pmax, ty0, ty1);

    float t_entry = fmaxf(tx0, ty0);
    float t_exit  = fminf(tx1, ty1);
    bool  alive   = t_entry < t_exit;
    float te  = alive ? t_entry : 0.0f;
    float tex = alive ? t_exit  : 0.0f;

    float xe = x0 + te * dx;
    float ye = y0 + te * dy;

    int i = (int)fminf(fmaxf(rintf(xe + 47.5f), 0.0f), (float)(Wd - 1));
    int j = (int)fminf(fmaxf(rintf(ye + 47.5f), 0.0f), (float)(Hd - 1));

    float x = xe, y = ye, t = te;
    float wscale = DIAG / fmaxf(fabsf(dx) + fabsf(dy), EPS);

    bool okx = fabsf(dx) > EPS;
    bool oky = fabsf(dy) > EPS;
    float inv_dx = okx ? (1.0f / dx) : 0.0f;
    float inv_dy = oky ? (1.0f / dy) : 0.0f;

    float xoff = (dx > 0.0f) ? (0.5f - 47.5f) : (-0.5f - 47.5f);
    float yoff = (dy > 0.0f) ? (0.5f - 47.5f) : (-0.5f - 47.5f);
    int   istep = (dx > 0.0f) ? 1 : -1;
    int   jstep = (dy > 0.0f) ? 1 : -1;

    int cnt  = 0;
    int base = r * NSTEPS;

    for (int s = 0; s < NSTEPS; s++) {
        if (!alive) break;
        bool valid = (t < tex - EPS);

        float tx = okx ? (((float)i + xoff) - x) * inv_dx : INFINITY;
        float ty = oky ? (((float)j + yoff) - y) * inv_dy : INFINITY;

        float dt = fminf(fminf(tx, ty), tex - t);
        float w  = fmaxf(0.0f, dt * wscale);

        if (valid && w > 0.0f) {
            int2 e;
            e.x = i * (Hd * Dd) + j * Dd;
            e.y = __float_as_int(w);
            g_trace[base + cnt] = e;
            cnt++;
        }

        int i_n = i + ((tx <= ty) ? istep : 0);
        int j_n = j + ((ty <= tx) ? jstep : 0);
        bool inb = (i_n >= 0) && (i_n < Wd) && (j_n >= 0) && (j_n < Hd);

        if (valid) {
            i = i_n; j = j_n;
            x += dx * dt;
            y += dy * dt;
            t += dt;
        }
        alive = valid && inb;
    }
    g_cnt[r] = cnt;
}

// One warp per ray. Lanes 0-15 handle even steps, 16-31 odd steps; each lane
// loads float4 (4 v-values) -> one LDG.128 warp-op covers 2 steps (512B).
// Trace padded in smem to a multiple of 8 with zero-weight entries.
__global__ __launch_bounds__(32 * WPB) void siddon_accum_kernel(
        const float* __restrict__ vol, float* __restrict__ out) {
    __shared__ int2 s_t[WPB][NPAD];

    int tid  = threadIdx.x;
    int wr   = tid >> 5;         // warp in block == ray slot
    int lane = tid & 31;
    int h    = lane >> 4;        // 0: even step, 1: odd step
    int vi   = lane & 15;        // float4 index over v

    int ray  = blockIdx.x * WPB + wr;
    int cnt  = g_cnt[ray];
    int base = ray * NSTEPS;
    int padded = (cnt + 7) & ~7;

    for (int n = lane; n < cnt; n += 32)
        s_t[wr][n] = g_trace[base + n];
    for (int n = cnt + lane; n < padded; n += 32)
        s_t[wr][n] = make_int2(0, 0);          // w = 0.0f -> contributes 0
    __syncwarp();

    const float4* vp4 = (const float4*)vol;

    float4 a0 = make_float4(0.f, 0.f, 0.f, 0.f);
    float4 a1 = make_float4(0.f, 0.f, 0.f, 0.f);
    float4 a2 = make_float4(0.f, 0.f, 0.f, 0.f);
    float4 a3 = make_float4(0.f, 0.f, 0.f, 0.f);

    for (int n = 0; n < padded; n += 8) {
        int2 e0 = s_t[wr][n + 0 + h];
        int2 e1 = s_t[wr][n + 2 + h];
        int2 e2 = s_t[wr][n + 4 + h];
        int2 e3 = s_t[wr][n + 6 + h];
        float4 v0 = vp4[(e0.x >> 2) + vi];
        float4 v1 = vp4[(e1.x >> 2) + vi];
        float4 v2 = vp4[(e2.x >> 2) + vi];
        float4 v3 = vp4[(e3.x >> 2) + vi];
        float w0 = __int_as_float(e0.y);
        float w1 = __int_as_float(e1.y);
        float w2 = __int_as_float(e2.y);
        float w3 = __int_as_float(e3.y);
        a0.x += v0.x * w0; a0.y += v0.y * w0; a0.z += v0.z * w0; a0.w += v0.w * w0;
        a1.x += v1.x * w1; a1.y += v1.y * w1; a1.z += v1.z * w1; a1.w += v1.w * w1;
        a2.x += v2.x * w2; a2.y += v2.y * w2; a2.z += v2.z * w2; a2.w += v2.w * w2;
        a3.x += v3.x * w3; a3.y += v3.y * w3; a3.z += v3.z * w3; a3.w += v3.w * w3;
    }

    float4 s;
    s.x = (a0.x + a1.x) + (a2.x + a3.x);
    s.y = (a0.y + a1.y) + (a2.y + a3.y);
    s.z = (a0.z + a1.z) + (a2.z + a3.z);
    s.w = (a0.w + a1.w) + (a2.w + a3.w);

    // Combine even-step and odd-step partials across half-warps.
    s.x += __shfl_xor_sync(0xFFFFFFFFu, s.x, 16);
    s.y += __shfl_xor_sync(0xFFFFFFFFu, s.y, 16);
    s.z += __shfl_xor_sync(0xFFFFFFFFu, s.z, 16);
    s.w += __shfl_xor_sync(0xFFFFFFFFu, s.w, 16);

    if (h == 0) {
        int a  = ray / Ud;
        int ui = ray % Ud;
        // output layout (B,C,U,A,V): float4 index = ((u*A + a)*V)/4 + vi
        ((float4*)out)[((ui * Ad + a) * Vd >> 2) + vi] = s;
    }
}

extern "C" void kernel_launch(void* const* d_in, const int* in_sizes, int n_in,
                              void* d_out, int out_size) {
    const float* vol = (const float*)d_in[0];
    float* out = (float*)d_out;

    siddon_trace_kernel<<<(NRAYS + 63) / 64, 64>>>();

    dim3 blk(32 * WPB);            // 128 threads
    dim3 grd(NRAYS / WPB);         // 2160 blocks
    siddon_accum_kernel<<<grd, blk>>>(vol, out);
}

// round 9
// speedup vs baseline: 1.9348x; 1.0063x over previous
#include <cuda_runtime.h>
#include <math.h>

// Problem constants (match reference)
#define Wd 96
#define Hd 96
#define Dd 64
#define Ad 90
#define Ud 96
#define Vd 64
#define NSTEPS 194          // H + W + 2
#define NRAYS  (Ad * Ud)    // 8640
#define RPB    4            // rays per block in accumulate kernel

// Static device scratch (no allocations allowed).
// Packed trace: .x = voxel base offset (i*H*D + j*D), .y = weight bits.
__device__ int2 g_trace[NRAYS * NSTEPS];
__device__ int  g_cnt[NRAYS];

__device__ __forceinline__ void t_for(float p0, float dp, float pmin, float pmax,
                                      float& lo, float& hi) {
    const float EPS = 1e-12f;
    bool par = fabsf(dp) < EPS;
    float safe = par ? 1.0f : dp;
    float t0 = (pmin - p0) / safe;
    float t1 = (pmax - p0) / safe;
    lo = fminf(t0, t1);
    hi = fmaxf(t0, t1);
    bool inside = (p0 >= pmin) && (p0 <= pmax);
    if (par) {
        lo = inside ? -INFINITY : INFINITY;
        hi = inside ?  INFINITY : -INFINITY;
    }
}

// One thread per ray. Branchless loop body (selects only), unconditional
// store each step, warp-uniform exit via vote -> no per-iteration BSSY/BSYNC.
__global__ __launch_bounds__(64) void siddon_trace_kernel() {
    int r = blockIdx.x * blockDim.x + threadIdx.x;
    if (r >= NRAYS) return;

    const float EPS  = 1e-12f;
    const float DIAG = 1.41421356237309515f;  // f32(sqrt(2))

    int a  = r / Ud;
    int ui = r % Ud;

    const float ang_step = 3.14159274101257324f / 90.0f;
    float ang = (float)a * ang_step;
    float ct = (float)cos((double)ang);
    float st = (float)sin((double)ang);

    float u  = (float)ui - 47.5f;
    float dx = ct, dy = st;
    float x0 = -u * st;
    float y0 =  u * ct;

    const float pmin = -47.5f, pmax = 47.5f;

    float tx0, tx1, ty0, ty1;
    t_for(x0, dx, pmin, pmax, tx0, tx1);
    t_for(y0, dy, pmin, pmax, ty0, ty1);

    float t_entry = fmaxf(tx0, ty0);
    float t_exit  = fminf(tx1, ty1);
    bool  alive   = t_entry < t_exit;
    float te  = alive ? t_entry : 0.0f;
    float tex = alive ? t_exit  : 0.0f;

    float xe = x0 + te * dx;
    float ye = y0 + te * dy;

    int i = (int)fminf(fmaxf(rintf(xe + 47.5f), 0.0f), (float)(Wd - 1));
    int j = (int)fminf(fmaxf(rintf(ye + 47.5f), 0.0f), (float)(Hd - 1));

    float x = xe, y = ye, t = te;
    float wscale = DIAG / fmaxf(fabsf(dx) + fabsf(dy), EPS);

    bool okx = fabsf(dx) > EPS;
    bool oky = fabsf(dy) > EPS;
    float inv_dx = okx ? (1.0f / dx) : 0.0f;
    float inv_dy = oky ? (1.0f / dy) : 0.0f;

    float xoff = (dx > 0.0f) ? (0.5f - 47.5f) : (-0.5f - 47.5f);
    float yoff = (dy > 0.0f) ? (0.5f - 47.5f) : (-0.5f - 47.5f);
    int   istep = (dx > 0.0f) ? 1 : -1;
    int   jstep = (dy > 0.0f) ? 1 : -1;

    int  nst  = 0;
    int  base = r * NSTEPS;

    #pragma unroll 1
    for (int s = 0; s < NSTEPS; s++) {
        bool valid = alive && (t < tex - EPS);

        float tx = okx ? (((float)i + xoff) - x) * inv_dx : INFINITY;
        float ty = oky ? (((float)j + yoff) - y) * inv_dy : INFINITY;

        float dt = fminf(fminf(tx, ty), tex - t);
        float w  = fmaxf(0.0f, dt * wscale);
        w = valid ? w : 0.0f;

        // Unconditional store: invalid/tie steps carry w=0 and are either
        // beyond nst or contribute exactly zero in the accumulator.
        int2 e;
        e.x = i * (Hd * Dd) + j * Dd;
        e.y = __float_as_int(w);
        g_trace[base + s] = e;
        nst = valid ? (s + 1) : nst;

        bool cx = (tx <= ty);
        bool cy = (ty <= tx);
        int i_n = i + (cx ? istep : 0);
        int j_n = j + (cy ? jstep : 0);
        bool inb = (i_n >= 0) && (i_n < Wd) && (j_n >= 0) && (j_n < Hd);

        float dts = valid ? dt : 0.0f;
        i = valid ? i_n : i;
        j = valid ? j_n : j;
        x += dx * dts;
        y += dy * dts;
        t += dts;
        alive = valid && inb;

        if (__all_sync(0xFFFFFFFFu, !alive)) break;   // warp-uniform exit
    }
    g_cnt[r] = nst;
}

// R2-proven accum kernel (19.7us): one warp per ray, float2 per lane.
__global__ __launch_bounds__(32 * RPB) void siddon_accum_kernel(
        const float* __restrict__ vol, float* __restrict__ out) {
    __shared__ int2 s_t[RPB][NSTEPS];

    int yy  = threadIdx.y;       // ray within block (== warp id)
    int x   = threadIdx.x;       // lane: covers v = 2x, 2x+1
    int ray = blockIdx.x * RPB + yy;

    int cnt  = g_cnt[ray];       // uniform per warp -> broadcast load
    int base = ray * NSTEPS;

    for (int n = x; n < cnt; n += 32)
        s_t[yy][n] = g_trace[base + n];
    __syncwarp();

    const float2* vp = (const float2*)vol;
    float a0x = 0.0f, a0y = 0.0f, a1x = 0.0f, a1y = 0.0f;

    int n = 0;
    for (; n + 1 < cnt; n += 2) {
        int2 e0 = s_t[yy][n + 0];
        int2 e1 = s_t[yy][n + 1];
        float2 v0 = vp[(e0.x >> 1) + x];
        float2 v1 = vp[(e1.x >> 1) + x];
        float  w0 = __int_as_float(e0.y);
        float  w1 = __int_as_float(e1.y);
        a0x += v0.x * w0;  a0y += v0.y * w0;
        a1x += v1.x * w1;  a1y += v1.y * w1;
    }
    if (n < cnt) {
        int2 e = s_t[yy][n];
        float2 v = vp[(e.x >> 1) + x];
        float  w = __int_as_float(e.y);
        a0x += v.x * w;  a0y += v.y * w;
    }

    int a  = ray / Ud;
    int ui = ray % Ud;
    float2 res;
    res.x = a0x + a1x;
    res.y = a0y + a1y;
    ((float2*)out)[(ui * Ad + a) * 32 + x] = res;
}

extern "C" void kernel_launch(void* const* d_in, const int* in_sizes, int n_in,
                              void* d_out, int out_size) {
    const float* vol = (const float*)d_in[0];
    float* out = (float*)d_out;

    siddon_trace_kernel<<<(NRAYS + 63) / 64, 64>>>();

    dim3 blk(32, RPB);                 // 128 threads
    dim3 grd(NRAYS / RPB);             // 2160 blocks
    siddon_accum_kernel<<<grd, blk>>>(vol, out);
}